// round 13
// baseline (speedup 1.0000x reference)
#include <cuda_runtime.h>
#include <cuda_fp16.h>
#include <cstdint>

#define N_NODES 50000
#define E_MAX   800000
#define D_IN 128
#define D_H 96
#define D_OUT 32

#define SCAN_B 256
#define NBLK ((N_NODES + SCAN_B - 1) / SCAN_B)   // 196

// ---------------------------------------------------------------------------
// Scratch (__device__ globals; allocation-free rule)
// g_deg invariant: ZERO at entry of every launch (zero-init at load; fill's
// atomicSub returns it to zero each launch). No zeroing kernel needed.
// ---------------------------------------------------------------------------
__device__ __half g_h1h[N_NODES * D_H];     // x @ W1, fp16
__device__ __half g_h2h[N_NODES * D_OUT];   // relu(A@h1) @ W2, fp16
__device__ int    g_deg[N_NODES];           // degree counts / fill cursor
__device__ int    g_start[N_NODES + 1];     // CSR row starts (by dst)
__device__ int    g_excl[N_NODES];          // block-local exclusive prescan
__device__ int    g_bsum[NBLK];             // per-block sums
__device__ int2   g_pair[E_MAX];            // per-edge {src, val_bits}

// ---------------------------------------------------------------------------
// Packed fp32x2 FMA (Blackwell): d.lo = a.lo*b.lo+c.lo, d.hi likewise.
// Exact fp32 arithmetic, 2 FMAs per instruction. Only reachable via PTX.
// ---------------------------------------------------------------------------
__device__ __forceinline__ uint64_t ffma2(uint64_t a, uint64_t b, uint64_t c) {
    uint64_t d;
    asm("fma.rn.f32x2 %0, %1, %2, %3;" : "=l"(d) : "l"(a), "l"(b), "l"(c));
    return d;
}

union F4U {
    float4 f;
    struct { uint64_t lo, hi; } u;   // lo = {f.x,f.y}, hi = {f.z,f.w}
};

// ---------------------------------------------------------------------------
// GEMM1: h1 = x @ W1   [50000,128]@[128,96], fp32 math (packed f32x2), fp16 out.
// blockDim (96,4). 8 rows x 1 col per thread; k processed in packed pairs:
// per thread per k4 step: 9 LDS.128 + 16 FFMA2 (was 32 FFMA).
// ---------------------------------------------------------------------------
#define G1_PAD  132   // 132 floats = 528 B, 16B-divisible (v4 alignment OK)
#define G1_ROWS 32
#define G1_ITER 2
#define G1_SMEM ((D_H * G1_PAD + G1_ROWS * G1_PAD) * sizeof(float))

__global__ void gemm1_kernel(const float* __restrict__ x,
                             const float* __restrict__ W1) {
    extern __shared__ float smem[];
    float* sWt = smem;                    // [96][132]  sWt[c][k] = W1[k][c]
    float* sx  = smem + D_H * G1_PAD;     // [32][132]

    const int tx = threadIdx.x, ty = threadIdx.y;
    const int t  = ty * 96 + tx;

    for (int i = t; i < D_IN * D_H; i += 384) {
        int k = i / D_H, c = i % D_H;
        sWt[c * G1_PAD + k] = W1[i];
    }
    __syncthreads();

    for (int it = 0; it < G1_ITER; it++) {
        int rowBase = (blockIdx.x * G1_ITER + it) * G1_ROWS;

        for (int i = t; i < G1_ROWS * D_IN; i += 384) {
            int r = i >> 7, k = i & 127;
            int row = rowBase + r;
            sx[r * G1_PAD + k] = (row < N_NODES) ? x[row * D_IN + k] : 0.f;
        }
        __syncthreads();

        uint64_t acc2[8];
        const float4* xr[8];
#pragma unroll
        for (int r = 0; r < 8; r++) {
            acc2[r] = 0ull;                       // packed {0.f, 0.f}
            xr[r] = (const float4*)(sx + (ty * 8 + r) * G1_PAD);
        }
        const float4* wrow = (const float4*)(sWt + tx * G1_PAD);

#pragma unroll 8
        for (int k4 = 0; k4 < D_IN / 4; k4++) {
            F4U w; w.f = wrow[k4];
#pragma unroll
            for (int r = 0; r < 8; r++) {
                F4U v; v.f = xr[r][k4];
                acc2[r] = ffma2(v.u.lo, w.u.lo, acc2[r]);
                acc2[r] = ffma2(v.u.hi, w.u.hi, acc2[r]);
            }
        }

        int r0 = rowBase + ty * 8;
#pragma unroll
        for (int r = 0; r < 8; r++) {
            if (r0 + r < N_NODES) {
                float lo = __uint_as_float((uint32_t)acc2[r]);
                float hi = __uint_as_float((uint32_t)(acc2[r] >> 32));
                g_h1h[(r0 + r) * D_H + tx] = __float2half_rn(lo + hi);
            }
        }
        __syncthreads();
    }
}

// ---------------------------------------------------------------------------
// CSR build: count -> block_scan -> finalize(w/ inline bsum reduce) -> fill
// ---------------------------------------------------------------------------
__global__ void count_kernel(const int* __restrict__ dst, int n_edges) {
    int e = blockIdx.x * blockDim.x + threadIdx.x;
    if (e < n_edges) atomicAdd(&g_deg[dst[e]], 1);
}

__global__ void block_scan_kernel() {
    __shared__ int ws[8];
    int i = blockIdx.x * SCAN_B + threadIdx.x;
    int v = (i < N_NODES) ? g_deg[i] : 0;
    int lane = threadIdx.x & 31, wid = threadIdx.x >> 5;

    int inc = v;
#pragma unroll
    for (int off = 1; off < 32; off <<= 1) {
        int n = __shfl_up_sync(0xffffffffu, inc, off);
        if (lane >= off) inc += n;
    }
    if (lane == 31) ws[wid] = inc;
    __syncthreads();
    if (wid == 0) {
        int s = (lane < 8) ? ws[lane] : 0;
#pragma unroll
        for (int off = 1; off < 8; off <<= 1) {
            int n = __shfl_up_sync(0xffffffffu, s, off);
            if (lane >= off) s += n;
        }
        if (lane < 8) ws[lane] = s;
    }
    __syncthreads();

    int woff = (wid == 0) ? 0 : ws[wid - 1];
    if (i < N_NODES) g_excl[i] = woff + inc - v;
    if (threadIdx.x == SCAN_B - 1) g_bsum[blockIdx.x] = ws[7];
}

__global__ void finalize_start_kernel(int n_edges) {
    __shared__ int sp[SCAN_B];
    int bid = blockIdx.x;
    int t = threadIdx.x;

    sp[t] = (t < bid && t < NBLK) ? g_bsum[t] : 0;
    __syncthreads();
#pragma unroll
    for (int off = SCAN_B / 2; off > 0; off >>= 1) {
        if (t < off) sp[t] += sp[t + off];
        __syncthreads();
    }
    int boff = sp[0];

    int i = bid * SCAN_B + t;
    if (i < N_NODES) g_start[i] = g_excl[i] + boff;
    if (i == 0) g_start[N_NODES] = n_edges;
}

// fill uses atomicSub: cursor runs deg -> 0, restoring the g_deg==0 invariant.
__global__ void fill_kernel(const int* __restrict__ src,
                            const int* __restrict__ dst,
                            const float* __restrict__ val,
                            int n_edges) {
    int e = blockIdx.x * blockDim.x + threadIdx.x;
    if (e >= n_edges) return;
    int d = dst[e];
    int pos = g_start[d] + atomicSub(&g_deg[d], 1) - 1;
    g_pair[pos] = make_int2(src[e], __float_as_int(val[e]));
}

// ---------------------------------------------------------------------------
// Fused layer 1 aggregation + relu + GEMM2 (fp16 h1 gathers, fp32 accum):
//   h2[n] = relu( sum_e val_e * h1[src_e] ) @ W2
// One warp per node, 32 warps/block. Lanes 0..23 gather 8B (4 fp16) per edge,
// 4-edge unroll; row staged in per-warp smem; lane c = output col c.
// ---------------------------------------------------------------------------
#define FW_WARPS 32
#define SROW_PAD 100

__device__ __forceinline__ void f16x4_fma(uint2 raw, float v,
                                          float& ax, float& ay,
                                          float& az, float& aw) {
    float2 f0 = __half22float2(*reinterpret_cast<const __half2*>(&raw.x));
    float2 f1 = __half22float2(*reinterpret_cast<const __half2*>(&raw.y));
    ax = fmaf(v, f0.x, ax); ay = fmaf(v, f0.y, ay);
    az = fmaf(v, f1.x, az); aw = fmaf(v, f1.y, aw);
}

__global__ void __launch_bounds__(FW_WARPS * 32)
fused_agg_gemm2_kernel(const float* __restrict__ W2) {
    __shared__ float sW2[D_H * D_OUT];              // [96][32], 12 KB
    __shared__ float srow[FW_WARPS][SROW_PAD];      // per-warp agg row, 12.8 KB

    int t = threadIdx.x;
    for (int i = t; i < D_H * D_OUT; i += blockDim.x) sW2[i] = W2[i];
    __syncthreads();

    int w    = t >> 5;
    int lane = t & 31;
    int n    = blockIdx.x * FW_WARPS + w;
    if (n >= N_NODES) return;

    const int2* __restrict__ pp = g_pair;
    int pBeg = g_start[n];
    int pEnd = g_start[n + 1];

    float ax = 0.f, ay = 0.f, az = 0.f, aw = 0.f;
    if (lane < 24) {
        int p = pBeg;
        for (; p + 3 < pEnd; p += 4) {
            int2 p0 = pp[p],     p1 = pp[p + 1];
            int2 p2 = pp[p + 2], p3 = pp[p + 3];
            uint2 r0 = *reinterpret_cast<const uint2*>(g_h1h + (long)p0.x * D_H + lane * 4);
            uint2 r1 = *reinterpret_cast<const uint2*>(g_h1h + (long)p1.x * D_H + lane * 4);
            uint2 r2 = *reinterpret_cast<const uint2*>(g_h1h + (long)p2.x * D_H + lane * 4);
            uint2 r3 = *reinterpret_cast<const uint2*>(g_h1h + (long)p3.x * D_H + lane * 4);
            f16x4_fma(r0, __int_as_float(p0.y), ax, ay, az, aw);
            f16x4_fma(r1, __int_as_float(p1.y), ax, ay, az, aw);
            f16x4_fma(r2, __int_as_float(p2.y), ax, ay, az, aw);
            f16x4_fma(r3, __int_as_float(p3.y), ax, ay, az, aw);
        }
        for (; p < pEnd; p++) {
            int2 pr = pp[p];
            uint2 r = *reinterpret_cast<const uint2*>(g_h1h + (long)pr.x * D_H + lane * 4);
            f16x4_fma(r, __int_as_float(pr.y), ax, ay, az, aw);
        }
        float4 r = make_float4(fmaxf(ax, 0.f), fmaxf(ay, 0.f),
                               fmaxf(az, 0.f), fmaxf(aw, 0.f));
        *reinterpret_cast<float4*>(&srow[w][lane * 4]) = r;
    }
    __syncwarp();

    float acc = 0.f;
    const float4* sr4 = reinterpret_cast<const float4*>(&srow[w][0]);
#pragma unroll
    for (int k4 = 0; k4 < D_H / 4; k4++) {
        float4 s = sr4[k4];
        int k = k4 * 4;
        acc = fmaf(s.x, sW2[(k + 0) * D_OUT + lane], acc);
        acc = fmaf(s.y, sW2[(k + 1) * D_OUT + lane], acc);
        acc = fmaf(s.z, sW2[(k + 2) * D_OUT + lane], acc);
        acc = fmaf(s.w, sW2[(k + 3) * D_OUT + lane], acc);
    }
    g_h2h[(long)n * D_OUT + lane] = __float2half_rn(acc);
}

// ---------------------------------------------------------------------------
// Layer 2 aggregation (gather): out[n] = sum val_e * h2[src_e]. One warp/node,
// lane = column (coalesced 64B fp16 gathers), 4-edge unroll, fp32 accum.
// ---------------------------------------------------------------------------
__global__ void __launch_bounds__(FW_WARPS * 32)
spmm2_gather_kernel(float* __restrict__ out) {
    int t    = threadIdx.x;
    int w    = t >> 5;
    int lane = t & 31;
    int n    = blockIdx.x * FW_WARPS + w;
    if (n >= N_NODES) return;

    const int2* __restrict__ pp = g_pair;
    int pBeg = g_start[n];
    int pEnd = g_start[n + 1];

    float acc = 0.f;
    int p = pBeg;
    for (; p + 3 < pEnd; p += 4) {
        int2 p0 = pp[p],     p1 = pp[p + 1];
        int2 p2 = pp[p + 2], p3 = pp[p + 3];
        float h0 = __half2float(g_h2h[(long)p0.x * D_OUT + lane]);
        float h1 = __half2float(g_h2h[(long)p1.x * D_OUT + lane]);
        float h2 = __half2float(g_h2h[(long)p2.x * D_OUT + lane]);
        float h3 = __half2float(g_h2h[(long)p3.x * D_OUT + lane]);
        acc = fmaf(__int_as_float(p0.y), h0, acc);
        acc = fmaf(__int_as_float(p1.y), h1, acc);
        acc = fmaf(__int_as_float(p2.y), h2, acc);
        acc = fmaf(__int_as_float(p3.y), h3, acc);
    }
    for (; p < pEnd; p++) {
        int2 pr = pp[p];
        acc = fmaf(__int_as_float(pr.y),
                   __half2float(g_h2h[(long)pr.x * D_OUT + lane]), acc);
    }
    out[(long)n * D_OUT + lane] = acc;
}

// ---------------------------------------------------------------------------
// Launch: single stream, 7 kernels:
// count -> gemm1 -> block_scan -> finalize -> fill -> fused_agg -> spmm2
// ---------------------------------------------------------------------------
extern "C" void kernel_launch(void* const* d_in, const int* in_sizes, int n_in,
                              void* d_out, int out_size) {
    const float* x        = (const float*)d_in[0];
    const int*   edge_src = (const int*)  d_in[1];
    const int*   edge_dst = (const int*)  d_in[2];
    const float* edge_val = (const float*)d_in[3];
    const float* W1       = (const float*)d_in[4];
    const float* W2       = (const float*)d_in[5];
    float*       out      = (float*)d_out;

    int E = in_sizes[1];

    static bool s_init = false;
    if (!s_init) {
        cudaFuncSetAttribute(gemm1_kernel,
                             cudaFuncAttributeMaxDynamicSharedMemorySize,
                             (int)G1_SMEM);
        s_init = true;
    }

    count_kernel<<<(E + 255) / 256, 256>>>(edge_dst, E);

    dim3 g1_block(96, 4);
    int  g1_grid = (N_NODES + G1_ROWS * G1_ITER - 1) / (G1_ROWS * G1_ITER);
    gemm1_kernel<<<g1_grid, g1_block, G1_SMEM>>>(x, W1);

    block_scan_kernel<<<NBLK, SCAN_B>>>();
    finalize_start_kernel<<<NBLK, SCAN_B>>>(E);
    fill_kernel<<<(E + 255) / 256, 256>>>(edge_src, edge_dst, edge_val, E);

    int fw_grid = (N_NODES + FW_WARPS - 1) / FW_WARPS;
    fused_agg_gemm2_kernel<<<fw_grid, FW_WARPS * 32>>>(W2);

    spmm2_gather_kernel<<<fw_grid, FW_WARPS * 32>>>(out);
}

// round 15
// speedup vs baseline: 1.4527x; 1.4527x over previous
#include <cuda_runtime.h>
#include <cuda_fp16.h>
#include <cstdint>

#define N_NODES 50000
#define E_MAX   800000
#define D_IN 128
#define D_H 96
#define D_OUT 32

#define SCAN_B 256
#define NBLK ((N_NODES + SCAN_B - 1) / SCAN_B)   // 196

// ---------------------------------------------------------------------------
// Scratch (__device__ globals; allocation-free rule)
// g_deg invariant: ZERO at entry of every launch (zero-init at load; fill's
// atomicSub returns it to zero each launch).
// ---------------------------------------------------------------------------
__device__ __half g_h1h[N_NODES * D_H];     // x @ W1, fp16
__device__ __half g_h2h[N_NODES * D_OUT];   // relu(A@h1) @ W2, fp16
__device__ int    g_deg[N_NODES];           // degree counts / fill cursor
__device__ int    g_start[N_NODES + 1];     // CSR row starts (by dst)
__device__ int    g_excl[N_NODES];          // block-local exclusive prescan
__device__ int    g_bsum[NBLK];             // per-block sums
__device__ int2   g_pair[E_MAX];            // per-edge {src, val_bits}

// ---------------------------------------------------------------------------
// GEMM1 via HMMA (mma.sync.m16n8k16, plain compute_100 PTX, sm_80+):
// per block (256 thr, 8 warps): h1[128 rows][96 cols], K=128, fp32 accum.
// A = x tile fp16 smem [128][136] row-major; B = W1^T fp16 smem [96][136]
// (n-major, k contiguous == col-major B for the row.col mma).
// Fragment maps (PTX ISA): group g=lane/4, pair tq=(lane%4)*2:
//   a0={A[g][k0+tq..+1]}  a1=row g+8  a2=k+8  a3=row+8,k+8
//   b0={B^T[n0+g][k0+tq..+1]}  b1=k+8
//   c0,c1=(row g, col tq,tq+1)  c2,c3=(row g+8)
// ---------------------------------------------------------------------------
#define G1_APITCH 136
#define G1_SA_ELEMS (128 * G1_APITCH)            // 17408 halves
#define G1_SMEM ((G1_SA_ELEMS + D_H * G1_APITCH) * sizeof(__half))  // ~60.9 KB

__global__ void __launch_bounds__(256)
gemm1_hmma_kernel(const float* __restrict__ x, const float* __restrict__ W1) {
    extern __shared__ __half smh[];
    __half* sA = smh;                    // [128][136]
    __half* sB = smh + G1_SA_ELEMS;      // [96][136]

    int tid = threadIdx.x, wid = tid >> 5, lane = tid & 31;
    int rowBase = blockIdx.x * 128;

    // A: x tile fp32 -> fp16, row-major padded. 2048 chunks of 8 cols.
    for (int ch = tid; ch < 2048; ch += 256) {
        int row = ch >> 4;
        int col0 = (ch & 15) * 8;
        int grow = rowBase + row;
        float4 f0, f1;
        if (grow < N_NODES) {
            const float4* xp = (const float4*)(x + (long)grow * D_IN + col0);
            f0 = xp[0]; f1 = xp[1];
        } else {
            f0 = make_float4(0.f, 0.f, 0.f, 0.f); f1 = f0;
        }
        __half2 h0 = __floats2half2_rn(f0.x, f0.y);
        __half2 h1 = __floats2half2_rn(f0.z, f0.w);
        __half2 h2 = __floats2half2_rn(f1.x, f1.y);
        __half2 h3 = __floats2half2_rn(f1.z, f1.w);
        uint4 v;
        v.x = *(uint32_t*)&h0; v.y = *(uint32_t*)&h1;
        v.z = *(uint32_t*)&h2; v.w = *(uint32_t*)&h3;
        *(uint4*)(sA + row * G1_APITCH + col0) = v;   // pitch 272B, 16B-divisible
    }

    // B: W1[k][c] -> sB[c][k] fp16 (scatter transpose).
    for (int i = tid; i < D_IN * D_H; i += 256) {
        int k = i / D_H, c = i - k * D_H;
        sB[c * G1_APITCH + k] = __float2half_rn(W1[i]);
    }
    __syncthreads();

    // Compute: warp wid owns rows [wid*16, wid*16+16).
    int g  = lane >> 2;          // 0..7
    int tq = (lane & 3) * 2;     // 0,2,4,6
    int warpRow = wid * 16;

    float c[12][4];
#pragma unroll
    for (int nt = 0; nt < 12; nt++) {
        c[nt][0] = 0.f; c[nt][1] = 0.f; c[nt][2] = 0.f; c[nt][3] = 0.f;
    }

    const __half* arow0 = sA + (warpRow + g) * G1_APITCH + tq;
    const __half* arow1 = arow0 + 8 * G1_APITCH;

#pragma unroll
    for (int ks = 0; ks < 8; ks++) {
        int k0 = ks * 16;
        uint32_t a0 = *(const uint32_t*)(arow0 + k0);
        uint32_t a1 = *(const uint32_t*)(arow1 + k0);
        uint32_t a2 = *(const uint32_t*)(arow0 + k0 + 8);
        uint32_t a3 = *(const uint32_t*)(arow1 + k0 + 8);
#pragma unroll
        for (int nt = 0; nt < 12; nt++) {
            const __half* brow = sB + (nt * 8 + g) * G1_APITCH + tq + k0;
            uint32_t b0 = *(const uint32_t*)(brow);
            uint32_t b1 = *(const uint32_t*)(brow + 8);
            asm volatile(
                "mma.sync.aligned.m16n8k16.row.col.f32.f16.f16.f32 "
                "{%0,%1,%2,%3}, {%4,%5,%6,%7}, {%8,%9}, {%0,%1,%2,%3};"
                : "+f"(c[nt][0]), "+f"(c[nt][1]), "+f"(c[nt][2]), "+f"(c[nt][3])
                : "r"(a0), "r"(a1), "r"(a2), "r"(a3), "r"(b0), "r"(b1));
        }
    }

    // Epilogue: fp16 stores, half2 per (c0,c1) / (c2,c3).
    int r0 = rowBase + warpRow + g;
    int r1 = r0 + 8;
#pragma unroll
    for (int nt = 0; nt < 12; nt++) {
        int col = nt * 8 + tq;
        if (r0 < N_NODES)
            *(__half2*)(g_h1h + (long)r0 * D_H + col) = __floats2half2_rn(c[nt][0], c[nt][1]);
        if (r1 < N_NODES)
            *(__half2*)(g_h1h + (long)r1 * D_H + col) = __floats2half2_rn(c[nt][2], c[nt][3]);
    }
}

// ---------------------------------------------------------------------------
// CSR build: count -> block_scan -> finalize(w/ inline bsum reduce) -> fill
// ---------------------------------------------------------------------------
__global__ void count_kernel(const int* __restrict__ dst, int n_edges) {
    int e = blockIdx.x * blockDim.x + threadIdx.x;
    if (e < n_edges) atomicAdd(&g_deg[dst[e]], 1);
}

__global__ void block_scan_kernel() {
    __shared__ int ws[8];
    int i = blockIdx.x * SCAN_B + threadIdx.x;
    int v = (i < N_NODES) ? g_deg[i] : 0;
    int lane = threadIdx.x & 31, wid = threadIdx.x >> 5;

    int inc = v;
#pragma unroll
    for (int off = 1; off < 32; off <<= 1) {
        int n = __shfl_up_sync(0xffffffffu, inc, off);
        if (lane >= off) inc += n;
    }
    if (lane == 31) ws[wid] = inc;
    __syncthreads();
    if (wid == 0) {
        int s = (lane < 8) ? ws[lane] : 0;
#pragma unroll
        for (int off = 1; off < 8; off <<= 1) {
            int n = __shfl_up_sync(0xffffffffu, s, off);
            if (lane >= off) s += n;
        }
        if (lane < 8) ws[lane] = s;
    }
    __syncthreads();

    int woff = (wid == 0) ? 0 : ws[wid - 1];
    if (i < N_NODES) g_excl[i] = woff + inc - v;
    if (threadIdx.x == SCAN_B - 1) g_bsum[blockIdx.x] = ws[7];
}

__global__ void finalize_start_kernel(int n_edges) {
    __shared__ int sp[SCAN_B];
    int bid = blockIdx.x;
    int t = threadIdx.x;

    sp[t] = (t < bid && t < NBLK) ? g_bsum[t] : 0;
    __syncthreads();
#pragma unroll
    for (int off = SCAN_B / 2; off > 0; off >>= 1) {
        if (t < off) sp[t] += sp[t + off];
        __syncthreads();
    }
    int boff = sp[0];

    int i = bid * SCAN_B + t;
    if (i < N_NODES) g_start[i] = g_excl[i] + boff;
    if (i == 0) g_start[N_NODES] = n_edges;
}

__global__ void fill_kernel(const int* __restrict__ src,
                            const int* __restrict__ dst,
                            const float* __restrict__ val,
                            int n_edges) {
    int e = blockIdx.x * blockDim.x + threadIdx.x;
    if (e >= n_edges) return;
    int d = dst[e];
    int pos = g_start[d] + atomicSub(&g_deg[d], 1) - 1;
    g_pair[pos] = make_int2(src[e], __float_as_int(val[e]));
}

// ---------------------------------------------------------------------------
// Fused layer 1 aggregation + relu + GEMM2 (fp16 h1 gathers, fp32 accum).
// ---------------------------------------------------------------------------
#define FW_WARPS 32
#define SROW_PAD 100

__device__ __forceinline__ void f16x4_fma(uint2 raw, float v,
                                          float& ax, float& ay,
                                          float& az, float& aw) {
    float2 f0 = __half22float2(*reinterpret_cast<const __half2*>(&raw.x));
    float2 f1 = __half22float2(*reinterpret_cast<const __half2*>(&raw.y));
    ax = fmaf(v, f0.x, ax); ay = fmaf(v, f0.y, ay);
    az = fmaf(v, f1.x, az); aw = fmaf(v, f1.y, aw);
}

__global__ void __launch_bounds__(FW_WARPS * 32)
fused_agg_gemm2_kernel(const float* __restrict__ W2) {
    __shared__ float sW2[D_H * D_OUT];
    __shared__ float srow[FW_WARPS][SROW_PAD];

    int t = threadIdx.x;
    for (int i = t; i < D_H * D_OUT; i += blockDim.x) sW2[i] = W2[i];
    __syncthreads();

    int w    = t >> 5;
    int lane = t & 31;
    int n    = blockIdx.x * FW_WARPS + w;
    if (n >= N_NODES) return;

    const int2* __restrict__ pp = g_pair;
    int pBeg = g_start[n];
    int pEnd = g_start[n + 1];

    float ax = 0.f, ay = 0.f, az = 0.f, aw = 0.f;
    if (lane < 24) {
        int p = pBeg;
        for (; p + 3 < pEnd; p += 4) {
            int2 p0 = pp[p],     p1 = pp[p + 1];
            int2 p2 = pp[p + 2], p3 = pp[p + 3];
            uint2 r0 = *reinterpret_cast<const uint2*>(g_h1h + (long)p0.x * D_H + lane * 4);
            uint2 r1 = *reinterpret_cast<const uint2*>(g_h1h + (long)p1.x * D_H + lane * 4);
            uint2 r2 = *reinterpret_cast<const uint2*>(g_h1h + (long)p2.x * D_H + lane * 4);
            uint2 r3 = *reinterpret_cast<const uint2*>(g_h1h + (long)p3.x * D_H + lane * 4);
            f16x4_fma(r0, __int_as_float(p0.y), ax, ay, az, aw);
            f16x4_fma(r1, __int_as_float(p1.y), ax, ay, az, aw);
            f16x4_fma(r2, __int_as_float(p2.y), ax, ay, az, aw);
            f16x4_fma(r3, __int_as_float(p3.y), ax, ay, az, aw);
        }
        for (; p < pEnd; p++) {
            int2 pr = pp[p];
            uint2 r = *reinterpret_cast<const uint2*>(g_h1h + (long)pr.x * D_H + lane * 4);
            f16x4_fma(r, __int_as_float(pr.y), ax, ay, az, aw);
        }
        float4 r = make_float4(fmaxf(ax, 0.f), fmaxf(ay, 0.f),
                               fmaxf(az, 0.f), fmaxf(aw, 0.f));
        *reinterpret_cast<float4*>(&srow[w][lane * 4]) = r;
    }
    __syncwarp();

    float acc = 0.f;
    const float4* sr4 = reinterpret_cast<const float4*>(&srow[w][0]);
#pragma unroll
    for (int k4 = 0; k4 < D_H / 4; k4++) {
        float4 s = sr4[k4];
        int k = k4 * 4;
        acc = fmaf(s.x, sW2[(k + 0) * D_OUT + lane], acc);
        acc = fmaf(s.y, sW2[(k + 1) * D_OUT + lane], acc);
        acc = fmaf(s.z, sW2[(k + 2) * D_OUT + lane], acc);
        acc = fmaf(s.w, sW2[(k + 3) * D_OUT + lane], acc);
    }
    g_h2h[(long)n * D_OUT + lane] = __float2half_rn(acc);
}

// ---------------------------------------------------------------------------
// Layer 2 aggregation (gather), fp16 h2, fp32 accum.
// ---------------------------------------------------------------------------
__global__ void __launch_bounds__(FW_WARPS * 32)
spmm2_gather_kernel(float* __restrict__ out) {
    int t    = threadIdx.x;
    int w    = t >> 5;
    int lane = t & 31;
    int n    = blockIdx.x * FW_WARPS + w;
    if (n >= N_NODES) return;

    const int2* __restrict__ pp = g_pair;
    int pBeg = g_start[n];
    int pEnd = g_start[n + 1];

    float acc = 0.f;
    int p = pBeg;
    for (; p + 3 < pEnd; p += 4) {
        int2 p0 = pp[p],     p1 = pp[p + 1];
        int2 p2 = pp[p + 2], p3 = pp[p + 3];
        float h0 = __half2float(g_h2h[(long)p0.x * D_OUT + lane]);
        float h1 = __half2float(g_h2h[(long)p1.x * D_OUT + lane]);
        float h2 = __half2float(g_h2h[(long)p2.x * D_OUT + lane]);
        float h3 = __half2float(g_h2h[(long)p3.x * D_OUT + lane]);
        acc = fmaf(__int_as_float(p0.y), h0, acc);
        acc = fmaf(__int_as_float(p1.y), h1, acc);
        acc = fmaf(__int_as_float(p2.y), h2, acc);
        acc = fmaf(__int_as_float(p3.y), h3, acc);
    }
    for (; p < pEnd; p++) {
        int2 pr = pp[p];
        acc = fmaf(__int_as_float(pr.y),
                   __half2float(g_h2h[(long)pr.x * D_OUT + lane]), acc);
    }
    out[(long)n * D_OUT + lane] = acc;
}

// ---------------------------------------------------------------------------
// Launch: count -> gemm1_hmma -> block_scan -> finalize -> fill -> fused -> spmm2
// ---------------------------------------------------------------------------
extern "C" void kernel_launch(void* const* d_in, const int* in_sizes, int n_in,
                              void* d_out, int out_size) {
    const float* x        = (const float*)d_in[0];
    const int*   edge_src = (const int*)  d_in[1];
    const int*   edge_dst = (const int*)  d_in[2];
    const float* edge_val = (const float*)d_in[3];
    const float* W1       = (const float*)d_in[4];
    const float* W2       = (const float*)d_in[5];
    float*       out      = (float*)d_out;

    int E = in_sizes[1];

    static bool s_init = false;
    if (!s_init) {
        cudaFuncSetAttribute(gemm1_hmma_kernel,
                             cudaFuncAttributeMaxDynamicSharedMemorySize,
                             (int)G1_SMEM);
        s_init = true;
    }

    count_kernel<<<(E + 255) / 256, 256>>>(edge_dst, E);

    int g1_grid = (N_NODES + 127) / 128;   // 391
    gemm1_hmma_kernel<<<g1_grid, 256, G1_SMEM>>>(x, W1);

    block_scan_kernel<<<NBLK, SCAN_B>>>();
    finalize_start_kernel<<<NBLK, SCAN_B>>>(E);
    fill_kernel<<<(E + 255) / 256, 256>>>(edge_src, edge_dst, edge_val, E);

    int fw_grid = (N_NODES + FW_WARPS - 1) / FW_WARPS;
    fused_agg_gemm2_kernel<<<fw_grid, FW_WARPS * 32>>>(W2);

    spmm2_gather_kernel<<<fw_grid, FW_WARPS * 32>>>(out);
}